// round 13
// baseline (speedup 1.0000x reference)
#include <cuda_runtime.h>
#include <cuda_fp16.h>

#define NMAX 100000
#define EMAX 1000000
#define SLOT 64

// ---- scratch (device globals; no allocation allowed) ----
__device__ int     g_cnt[NMAX];                  // per-node in-degree (excl self loop)
__device__ int     g_colS[(size_t)NMAX * SLOT];  // slotted adjacency (src indices)
__device__ float   g_dinv[NMAX];                 // (deg incl self loop)^-1/2
__device__ __half2 g_t2[NMAX * 32];              // GEMM output fp16 (gather operand)
__device__ __half2 g_h2[NMAX * 32];              // activations fp16

// ---------------- graph build ----------------

__global__ void k_fill(const int* __restrict__ ei, int e) {
    int i = blockIdx.x * blockDim.x + threadIdx.x;
    if (i >= e) return;
    int src = ei[i];
    int dst = ei[e + i];
    int pos = atomicAdd(&g_cnt[dst], 1);
    if (pos < SLOT) g_colS[(size_t)dst * SLOT + pos] = src;
}

__global__ void k_dinv(int n) {
    int i = blockIdx.x * blockDim.x + threadIdx.x;
    if (i < n) g_dinv[i] = rsqrtf((float)(g_cnt[i] + 1));   // +1 = self loop
}

// ---------------- dense GEMM via HMMA: Y[n,F] = X[n,64] @ W[64,F] ----------------
// 256 threads / 8 warps, 128 rows/block; warp tile 16 x F; mma.m16n8k16 f16->f32.
// SCALE: multiply output row r by dinv[r] (pre-scaling for unweighted aggregation).

template <int F, bool HALF_IN, bool HALF_OUT, bool SCALE>
__global__ void __launch_bounds__(256) k_gemm_mma(
    const float* __restrict__ Xf, const __half2* __restrict__ Xh,
    const float* __restrict__ W, const float* __restrict__ bias,
    const float* __restrict__ dinv,
    float* __restrict__ Yf, __half2* __restrict__ Yh, int n)
{
    __shared__ __half Xs[128 * 72];   // 18 KB
    __shared__ __half Ws[F * 72];
    int t  = threadIdx.x;
    int r0 = blockIdx.x * 128;

    for (int i = t; i < 128 * 32; i += 256) {
        int r = i >> 5, c2 = i & 31;
        __half2 hv;
        if (r0 + r < n) {
            if (HALF_IN) {
                hv = Xh[(size_t)(r0 + r) * 32 + c2];
            } else {
                float2 v = *(const float2*)&Xf[(size_t)(r0 + r) * 64 + c2 * 2];
                hv = __floats2half2_rn(v.x, v.y);
            }
        } else {
            hv = __floats2half2_rn(0.f, 0.f);
        }
        *(__half2*)&Xs[r * 72 + c2 * 2] = hv;
    }
    for (int i = t; i < F * 32; i += 256) {
        int c = i % F, k2 = i / F;
        __half2 hv = __floats2half2_rn(W[(2 * k2) * F + c], W[(2 * k2 + 1) * F + c]);
        *(__half2*)&Ws[c * 72 + k2 * 2] = hv;
    }
    __syncthreads();

    int lane = t & 31, w = t >> 5;
    int rw = w * 16;
    int g  = lane >> 2;
    int qc = (lane & 3) * 2;
    constexpr int NT = F / 8;

    float acc[NT][4];
#pragma unroll
    for (int j = 0; j < NT; j++)
#pragma unroll
        for (int q = 0; q < 4; q++) acc[j][q] = 0.f;

#pragma unroll
    for (int kt = 0; kt < 4; kt++) {
        int kb = kt * 16;
        unsigned a0 = *(const unsigned*)&Xs[(rw + g) * 72 + kb + qc];
        unsigned a1 = *(const unsigned*)&Xs[(rw + g + 8) * 72 + kb + qc];
        unsigned a2 = *(const unsigned*)&Xs[(rw + g) * 72 + kb + qc + 8];
        unsigned a3 = *(const unsigned*)&Xs[(rw + g + 8) * 72 + kb + qc + 8];
#pragma unroll
        for (int j = 0; j < NT; j++) {
            unsigned b0 = *(const unsigned*)&Ws[(j * 8 + g) * 72 + kb + qc];
            unsigned b1 = *(const unsigned*)&Ws[(j * 8 + g) * 72 + kb + qc + 8];
            asm volatile(
                "mma.sync.aligned.m16n8k16.row.col.f32.f16.f16.f32 "
                "{%0,%1,%2,%3}, {%4,%5,%6,%7}, {%8,%9}, {%0,%1,%2,%3};"
                : "+f"(acc[j][0]), "+f"(acc[j][1]), "+f"(acc[j][2]), "+f"(acc[j][3])
                : "r"(a0), "r"(a1), "r"(a2), "r"(a3), "r"(b0), "r"(b1));
        }
    }

    int R0 = r0 + rw + g;
    int R1 = R0 + 8;
    if (HALF_OUT) {
        float s0 = 1.f, s1 = 1.f;
        if (SCALE) {
            if (R0 < n) s0 = dinv[R0];
            if (R1 < n) s1 = dinv[R1];
        }
#pragma unroll
        for (int j = 0; j < NT; j++) {
            int col2 = (j * 8 + qc) >> 1;
            if (R0 < n) Yh[(size_t)R0 * 32 + col2] =
                __floats2half2_rn(acc[j][0] * s0, acc[j][1] * s0);
            if (R1 < n) Yh[(size_t)R1 * 32 + col2] =
                __floats2half2_rn(acc[j][2] * s1, acc[j][3] * s1);
        }
    } else {
#pragma unroll
        for (int j = 0; j < NT; j++) {
            int col = j * 8 + qc;
            float bx = bias[col], by = bias[col + 1];
            if (R0 < n) *(float2*)&Yf[(size_t)R0 * F + col] =
                make_float2(acc[j][0] + bx, acc[j][1] + by);
            if (R1 < n) *(float2*)&Yf[(size_t)R1 * F + col] =
                make_float2(acc[j][2] + bx, acc[j][3] + by);
        }
    }
}

// ---------------- aggregation ----------------
// One warp per dst; 4 edges per iteration (group = lane>>3, 8 lanes x uint4 row).
// WEIGHTED: edge term = dinv[src]*t[src] (HFMA2, fp16 acc); else t prescaled (HADD2).
// Group partial sums in fp16 (<=16 terms), converted to fp32 before reduction.
// Self-loop handled in fp32 by group 0. Output fp16, relu(d*sum + b).

template <bool WEIGHTED>
__global__ void __launch_bounds__(256) k_agg(const __half2* __restrict__ t2,
                                             __half2* __restrict__ hout,
                                             const float* __restrict__ bias,
                                             int n) {
    int row  = (blockIdx.x * blockDim.x + threadIdx.x) >> 5;
    int lane = threadIdx.x & 31;
    if (row >= n) return;
    int group = lane >> 3;
    int fl    = lane & 7;
    int c = g_cnt[row];
    if (c > SLOT) c = SLOT;
    float d = g_dinv[row];
    const uint4* t4 = (const uint4*)t2;
    const int* colrow = &g_colS[(size_t)row * SLOT];

    __half2 hacc[4];
#pragma unroll
    for (int j = 0; j < 4; j++) hacc[j] = __floats2half2_rn(0.f, 0.f);

    for (int b = 0; b < c; b += 32) {
        int m = min(32, c - b);
        int   idx = (lane < m) ? colrow[b + lane] : 0;
        float wv  = WEIGHTED ? ((lane < m) ? g_dinv[idx] : 0.f) : 0.f;
        for (int u = 0; u < m; u += 4) {
            int sl = u + group;   // <= 31
            int src = __shfl_sync(0xffffffffu, idx, sl);
            uint4 v = t4[(size_t)src * 8 + fl];
            const __half2* hp = (const __half2*)&v;
            if (WEIGHTED) {
                float ww = __int_as_float(
                    __shfl_sync(0xffffffffu, __float_as_int(wv), sl));
                __half2 w2 = __half2half2(__float2half_rn(ww));
                hacc[0] = __hfma2(hp[0], w2, hacc[0]);
                hacc[1] = __hfma2(hp[1], w2, hacc[1]);
                hacc[2] = __hfma2(hp[2], w2, hacc[2]);
                hacc[3] = __hfma2(hp[3], w2, hacc[3]);
            } else {
                bool live = sl < m;   // pad groups must not add garbage
                if (live) {
                    hacc[0] = __hadd2(hacc[0], hp[0]);
                    hacc[1] = __hadd2(hacc[1], hp[1]);
                    hacc[2] = __hadd2(hacc[2], hp[2]);
                    hacc[3] = __hadd2(hacc[3], hp[3]);
                }
            }
        }
    }

    // fp16 partials -> fp32
    float acc[8];
#pragma unroll
    for (int j = 0; j < 4; j++) {
        float2 p = __half22float2(hacc[j]);
        acc[2 * j]     = p.x;
        acc[2 * j + 1] = p.y;
    }

    // self loop (group 0, fp32): weighted -> d*t[row]; unweighted -> t[row] (prescaled)
    if (group == 0) {
        uint4 v = t4[(size_t)row * 8 + fl];
        const __half2* hp = (const __half2*)&v;
        float sw = WEIGHTED ? d : 1.f;
        float2 a0 = __half22float2(hp[0]);
        float2 a1 = __half22float2(hp[1]);
        float2 a2 = __half22float2(hp[2]);
        float2 a3 = __half22float2(hp[3]);
        acc[0] = fmaf(sw, a0.x, acc[0]);
        acc[1] = fmaf(sw, a0.y, acc[1]);
        acc[2] = fmaf(sw, a1.x, acc[2]);
        acc[3] = fmaf(sw, a1.y, acc[3]);
        acc[4] = fmaf(sw, a2.x, acc[4]);
        acc[5] = fmaf(sw, a2.y, acc[5]);
        acc[6] = fmaf(sw, a3.x, acc[6]);
        acc[7] = fmaf(sw, a3.y, acc[7]);
    }

#pragma unroll
    for (int j = 0; j < 8; j++)
        acc[j] += __shfl_down_sync(0xffffffffu, acc[j], 16);
#pragma unroll
    for (int j = 0; j < 8; j++)
        acc[j] += __shfl_down_sync(0xffffffffu, acc[j], 8);

    if (lane < 8) {
        int f0 = lane * 8;
        float o[8];
#pragma unroll
        for (int j = 0; j < 8; j++)
            o[j] = fmaxf(fmaf(d, acc[j], bias[f0 + j]), 0.f);
        __half2 p0 = __floats2half2_rn(o[0], o[1]);
        __half2 p1 = __floats2half2_rn(o[2], o[3]);
        __half2 p2 = __floats2half2_rn(o[4], o[5]);
        __half2 p3 = __floats2half2_rn(o[6], o[7]);
        uint4 st = make_uint4(*(unsigned*)&p0, *(unsigned*)&p1,
                              *(unsigned*)&p2, *(unsigned*)&p3);
        *(uint4*)&hout[(size_t)row * 32 + lane * 4] = st;
    }
}

// ---------------- launch ----------------

extern "C" void kernel_launch(void* const* d_in, const int* in_sizes, int n_in,
                              void* d_out, int out_size) {
    const float* x  = (const float*)d_in[0];
    const int*   ei = (const int*)d_in[1];
    const float* W1 = (const float*)d_in[2];
    const float* b1 = (const float*)d_in[3];
    const float* W2 = (const float*)d_in[4];
    const float* b2 = (const float*)d_in[5];
    const float* Wl = (const float*)d_in[6];
    const float* bl = (const float*)d_in[7];
    float* out = (float*)d_out;

    int n = in_sizes[0] / 64;   // 100000
    int e = in_sizes[1] / 2;    // 1000000

    __half2* t2_ptr = nullptr;
    __half2* h2_ptr = nullptr;
    int*     cnt_ptr = nullptr;
    float*   dinv_ptr = nullptr;
    cudaGetSymbolAddress((void**)&t2_ptr, g_t2);
    cudaGetSymbolAddress((void**)&h2_ptr, g_h2);
    cudaGetSymbolAddress((void**)&cnt_ptr, g_cnt);
    cudaGetSymbolAddress((void**)&dinv_ptr, g_dinv);

    static cudaStream_t s_aux = nullptr;
    static cudaEvent_t  ev_fork = nullptr, ev_join = nullptr;
    if (s_aux == nullptr) {
        cudaStreamCreateWithFlags(&s_aux, cudaStreamNonBlocking);
        cudaEventCreateWithFlags(&ev_fork, cudaEventDisableTiming);
        cudaEventCreateWithFlags(&ev_join, cudaEventDisableTiming);
    }

    int nb = (n + 255) / 256;
    int gemm_blocks = (n + 127) / 128;
    int agg_blocks  = (n + 7) / 8;

    // fork: GEMM1 (t = x @ W1 -> fp16, unscaled) depends only on kernel inputs
    cudaEventRecord(ev_fork, 0);
    cudaStreamWaitEvent(s_aux, ev_fork, 0);
    k_gemm_mma<64, false, true, false><<<gemm_blocks, 256, 0, s_aux>>>(
        x, nullptr, W1, nullptr, nullptr, nullptr, t2_ptr, n);
    cudaEventRecord(ev_join, s_aux);

    // graph build on main stream (overlaps GEMM1)
    cudaMemsetAsync(cnt_ptr, 0, (size_t)n * sizeof(int));
    k_fill<<<(e + 255) / 256, 256>>>(ei, e);
    k_dinv<<<nb, 256>>>(n);

    // join, then serial tail
    cudaStreamWaitEvent(0, ev_join, 0);
    k_agg<true><<<agg_blocks, 256>>>(t2_ptr, h2_ptr, b1, n);
    // GEMM2 pre-scales its fp16 output rows by dinv[row] -> unweighted agg2
    k_gemm_mma<64, true, true, true><<<gemm_blocks, 256>>>(
        nullptr, h2_ptr, W2, nullptr, dinv_ptr, nullptr, t2_ptr, n);
    k_agg<false><<<agg_blocks, 256>>>(t2_ptr, h2_ptr, b2, n);
    k_gemm_mma<32, true, false, false><<<gemm_blocks, 256>>>(
        nullptr, h2_ptr, Wl, bl, nullptr, out, nullptr, n);
}

// round 14
// speedup vs baseline: 1.0159x; 1.0159x over previous
#include <cuda_runtime.h>
#include <cuda_fp16.h>

#define NMAX 100000
#define EMAX 1000000
#define SLOT 64

// ---- scratch (device globals; no allocation allowed) ----
__device__ int     g_cnt[NMAX];                  // per-node in-degree (excl self loop)
__device__ int     g_colS[(size_t)NMAX * SLOT];  // slotted adjacency (src indices)
__device__ float   g_dinv[NMAX];                 // (deg incl self loop)^-1/2
__device__ __half2 g_t2[(NMAX + 1) * 32];        // gather operand; row NMAX = zeros (pad)
__device__ __half2 g_h2[NMAX * 32];              // activations fp16

// ---------------- graph build ----------------

__global__ void k_fill(const int* __restrict__ ei, int e) {
    int i = blockIdx.x * blockDim.x + threadIdx.x;
    if (i >= e) return;
    int src = ei[i];
    int dst = ei[e + i];
    int pos = atomicAdd(&g_cnt[dst], 1);
    if (pos < SLOT) g_colS[(size_t)dst * SLOT + pos] = src;
}

__global__ void k_dinv(int n) {
    int i = blockIdx.x * blockDim.x + threadIdx.x;
    if (i < n) g_dinv[i] = rsqrtf((float)(g_cnt[i] + 1));   // +1 = self loop
}

// ---------------- prescale: t2[row] *= dinv[row] (one uint4 = 8 halves per thread) ----------------

__global__ void __launch_bounds__(256) k_scale(__half2* __restrict__ t2, int n) {
    int i = blockIdx.x * blockDim.x + threadIdx.x;   // uint4 index
    if (i >= n * 8) return;
    int row = i >> 3;
    __half2 d2 = __half2half2(__float2half_rn(g_dinv[row]));
    uint4* p = (uint4*)t2 + i;
    uint4 v = *p;
    __half2* hp = (__half2*)&v;
    hp[0] = __hmul2(hp[0], d2);
    hp[1] = __hmul2(hp[1], d2);
    hp[2] = __hmul2(hp[2], d2);
    hp[3] = __hmul2(hp[3], d2);
    *p = v;
}

// ---------------- dense GEMM via HMMA: Y[n,F] = X[n,64] @ W[64,F] ----------------
// 256 threads / 8 warps, 128 rows/block; warp tile 16 x F; mma.m16n8k16 f16->f32.
// SCALE: multiply output row r by dinv[r] (pre-scaling for unweighted aggregation).

template <int F, bool HALF_IN, bool HALF_OUT, bool SCALE>
__global__ void __launch_bounds__(256) k_gemm_mma(
    const float* __restrict__ Xf, const __half2* __restrict__ Xh,
    const float* __restrict__ W, const float* __restrict__ bias,
    const float* __restrict__ dinv,
    float* __restrict__ Yf, __half2* __restrict__ Yh, int n)
{
    __shared__ __half Xs[128 * 72];   // 18 KB
    __shared__ __half Ws[F * 72];
    int t  = threadIdx.x;
    int r0 = blockIdx.x * 128;

    for (int i = t; i < 128 * 32; i += 256) {
        int r = i >> 5, c2 = i & 31;
        __half2 hv;
        if (r0 + r < n) {
            if (HALF_IN) {
                hv = Xh[(size_t)(r0 + r) * 32 + c2];
            } else {
                float2 v = *(const float2*)&Xf[(size_t)(r0 + r) * 64 + c2 * 2];
                hv = __floats2half2_rn(v.x, v.y);
            }
        } else {
            hv = __floats2half2_rn(0.f, 0.f);
        }
        *(__half2*)&Xs[r * 72 + c2 * 2] = hv;
    }
    for (int i = t; i < F * 32; i += 256) {
        int c = i % F, k2 = i / F;
        __half2 hv = __floats2half2_rn(W[(2 * k2) * F + c], W[(2 * k2 + 1) * F + c]);
        *(__half2*)&Ws[c * 72 + k2 * 2] = hv;
    }
    __syncthreads();

    int lane = t & 31, w = t >> 5;
    int rw = w * 16;
    int g  = lane >> 2;
    int qc = (lane & 3) * 2;
    constexpr int NT = F / 8;

    float acc[NT][4];
#pragma unroll
    for (int j = 0; j < NT; j++)
#pragma unroll
        for (int q = 0; q < 4; q++) acc[j][q] = 0.f;

#pragma unroll
    for (int kt = 0; kt < 4; kt++) {
        int kb = kt * 16;
        unsigned a0 = *(const unsigned*)&Xs[(rw + g) * 72 + kb + qc];
        unsigned a1 = *(const unsigned*)&Xs[(rw + g + 8) * 72 + kb + qc];
        unsigned a2 = *(const unsigned*)&Xs[(rw + g) * 72 + kb + qc + 8];
        unsigned a3 = *(const unsigned*)&Xs[(rw + g + 8) * 72 + kb + qc + 8];
#pragma unroll
        for (int j = 0; j < NT; j++) {
            unsigned b0 = *(const unsigned*)&Ws[(j * 8 + g) * 72 + kb + qc];
            unsigned b1 = *(const unsigned*)&Ws[(j * 8 + g) * 72 + kb + qc + 8];
            asm volatile(
                "mma.sync.aligned.m16n8k16.row.col.f32.f16.f16.f32 "
                "{%0,%1,%2,%3}, {%4,%5,%6,%7}, {%8,%9}, {%0,%1,%2,%3};"
                : "+f"(acc[j][0]), "+f"(acc[j][1]), "+f"(acc[j][2]), "+f"(acc[j][3])
                : "r"(a0), "r"(a1), "r"(a2), "r"(a3), "r"(b0), "r"(b1));
        }
    }

    int R0 = r0 + rw + g;
    int R1 = R0 + 8;
    if (HALF_OUT) {
        float s0 = 1.f, s1 = 1.f;
        if (SCALE) {
            if (R0 < n) s0 = dinv[R0];
            if (R1 < n) s1 = dinv[R1];
        }
#pragma unroll
        for (int j = 0; j < NT; j++) {
            int col2 = (j * 8 + qc) >> 1;
            if (R0 < n) Yh[(size_t)R0 * 32 + col2] =
                __floats2half2_rn(acc[j][0] * s0, acc[j][1] * s0);
            if (R1 < n) Yh[(size_t)R1 * 32 + col2] =
                __floats2half2_rn(acc[j][2] * s1, acc[j][3] * s1);
        }
    } else {
#pragma unroll
        for (int j = 0; j < NT; j++) {
            int col = j * 8 + qc;
            float bx = bias[col], by = bias[col + 1];
            if (R0 < n) *(float2*)&Yf[(size_t)R0 * F + col] =
                make_float2(acc[j][0] + bx, acc[j][1] + by);
            if (R1 < n) *(float2*)&Yf[(size_t)R1 * F + col] =
                make_float2(acc[j][2] + bx, acc[j][3] + by);
        }
    }
}

// ---------------- aggregation (unweighted; t prescaled by dinv[src]) ----------------
// One warp per dst; 4 edges per iteration (group = lane>>3, 8 lanes x uint4 row).
// Pad lanes index the zero row (NMAX) -> unconditional HADD2, no predicates.
// fp16 group partials (<=16 terms + self), fp32 cross-group reduction.
// h[dst] = relu(dinv[dst] * sum + b), stored fp16.

__global__ void __launch_bounds__(256) k_agg(const __half2* __restrict__ t2,
                                             __half2* __restrict__ hout,
                                             const float* __restrict__ bias,
                                             int n) {
    int row  = (blockIdx.x * blockDim.x + threadIdx.x) >> 5;
    int lane = threadIdx.x & 31;
    if (row >= n) return;
    int group = lane >> 3;
    int fl    = lane & 7;
    int c = g_cnt[row];
    if (c > SLOT) c = SLOT;
    float d = g_dinv[row];
    const uint4* t4 = (const uint4*)t2;
    const int* colrow = &g_colS[(size_t)row * SLOT];

    __half2 hacc[4];
#pragma unroll
    for (int j = 0; j < 4; j++) hacc[j] = __floats2half2_rn(0.f, 0.f);

    for (int b = 0; b < c; b += 32) {
        int m = min(32, c - b);
        int idx = (lane < m) ? colrow[b + lane] : NMAX;   // pad -> zero row
        for (int u = 0; u < m; u += 4) {
            int src = __shfl_sync(0xffffffffu, idx, u + group);
            uint4 v = t4[(size_t)src * 8 + fl];
            const __half2* hp = (const __half2*)&v;
            hacc[0] = __hadd2(hacc[0], hp[0]);
            hacc[1] = __hadd2(hacc[1], hp[1]);
            hacc[2] = __hadd2(hacc[2], hp[2]);
            hacc[3] = __hadd2(hacc[3], hp[3]);
        }
    }

    // self loop (group 0): prescaled t[row]
    if (group == 0) {
        uint4 v = t4[(size_t)row * 8 + fl];
        const __half2* hp = (const __half2*)&v;
        hacc[0] = __hadd2(hacc[0], hp[0]);
        hacc[1] = __hadd2(hacc[1], hp[1]);
        hacc[2] = __hadd2(hacc[2], hp[2]);
        hacc[3] = __hadd2(hacc[3], hp[3]);
    }

    // fp16 partials -> fp32, cross-group reduce
    float acc[8];
#pragma unroll
    for (int j = 0; j < 4; j++) {
        float2 p = __half22float2(hacc[j]);
        acc[2 * j]     = p.x;
        acc[2 * j + 1] = p.y;
    }
#pragma unroll
    for (int j = 0; j < 8; j++)
        acc[j] += __shfl_down_sync(0xffffffffu, acc[j], 16);
#pragma unroll
    for (int j = 0; j < 8; j++)
        acc[j] += __shfl_down_sync(0xffffffffu, acc[j], 8);

    if (lane < 8) {
        int f0 = lane * 8;
        float o[8];
#pragma unroll
        for (int j = 0; j < 8; j++)
            o[j] = fmaxf(fmaf(d, acc[j], bias[f0 + j]), 0.f);
        __half2 p0 = __floats2half2_rn(o[0], o[1]);
        __half2 p1 = __floats2half2_rn(o[2], o[3]);
        __half2 p2 = __floats2half2_rn(o[4], o[5]);
        __half2 p3 = __floats2half2_rn(o[6], o[7]);
        uint4 st = make_uint4(*(unsigned*)&p0, *(unsigned*)&p1,
                              *(unsigned*)&p2, *(unsigned*)&p3);
        *(uint4*)&hout[(size_t)row * 32 + lane * 4] = st;
    }
}

// ---------------- launch ----------------

extern "C" void kernel_launch(void* const* d_in, const int* in_sizes, int n_in,
                              void* d_out, int out_size) {
    const float* x  = (const float*)d_in[0];
    const int*   ei = (const int*)d_in[1];
    const float* W1 = (const float*)d_in[2];
    const float* b1 = (const float*)d_in[3];
    const float* W2 = (const float*)d_in[4];
    const float* b2 = (const float*)d_in[5];
    const float* Wl = (const float*)d_in[6];
    const float* bl = (const float*)d_in[7];
    float* out = (float*)d_out;

    int n = in_sizes[0] / 64;   // 100000
    int e = in_sizes[1] / 2;    // 1000000

    __half2* t2_ptr = nullptr;
    __half2* h2_ptr = nullptr;
    int*     cnt_ptr = nullptr;
    float*   dinv_ptr = nullptr;
    cudaGetSymbolAddress((void**)&t2_ptr, g_t2);
    cudaGetSymbolAddress((void**)&h2_ptr, g_h2);
    cudaGetSymbolAddress((void**)&cnt_ptr, g_cnt);
    cudaGetSymbolAddress((void**)&dinv_ptr, g_dinv);

    static cudaStream_t s_aux = nullptr;
    static cudaEvent_t  ev_fork = nullptr, ev_join = nullptr;
    if (s_aux == nullptr) {
        cudaStreamCreateWithFlags(&s_aux, cudaStreamNonBlocking);
        cudaEventCreateWithFlags(&ev_fork, cudaEventDisableTiming);
        cudaEventCreateWithFlags(&ev_join, cudaEventDisableTiming);
    }

    int nb = (n + 255) / 256;
    int gemm_blocks = (n + 127) / 128;
    int agg_blocks  = (n + 7) / 8;

    // fork: GEMM1 (t = x @ W1 -> fp16, unscaled) depends only on kernel inputs
    cudaEventRecord(ev_fork, 0);
    cudaStreamWaitEvent(s_aux, ev_fork, 0);
    k_gemm_mma<64, false, true, false><<<gemm_blocks, 256, 0, s_aux>>>(
        x, nullptr, W1, nullptr, nullptr, nullptr, t2_ptr, n);
    cudaEventRecord(ev_join, s_aux);

    // graph build on main stream (overlaps GEMM1); zero the pad row of t2
    cudaMemsetAsync(cnt_ptr, 0, (size_t)n * sizeof(int));
    cudaMemsetAsync(t2_ptr + (size_t)NMAX * 32, 0, 32 * sizeof(__half2));
    k_fill<<<(e + 255) / 256, 256>>>(ei, e);
    k_dinv<<<nb, 256>>>(n);

    // join; prescale t1 by dinv, then unweighted agg
    cudaStreamWaitEvent(0, ev_join, 0);
    k_scale<<<(n * 8 + 255) / 256, 256>>>(t2_ptr, n);
    k_agg<<<agg_blocks, 256>>>(t2_ptr, h2_ptr, b1, n);
    // GEMM2 pre-scales its fp16 output rows by dinv[row] in-epilogue
    k_gemm_mma<64, true, true, true><<<gemm_blocks, 256>>>(
        nullptr, h2_ptr, W2, nullptr, dinv_ptr, nullptr, t2_ptr, n);
    k_agg<<<agg_blocks, 256>>>(t2_ptr, h2_ptr, b2, n);
    k_gemm_mma<32, true, false, false><<<gemm_blocks, 256>>>(
        nullptr, h2_ptr, Wl, bl, nullptr, out, nullptr, n);
}

// round 15
// speedup vs baseline: 1.0497x; 1.0333x over previous
#include <cuda_runtime.h>
#include <cuda_fp16.h>

#define NMAX 100000
#define EMAX 1000000
#define SLOT 64

// ---- scratch (device globals; no allocation allowed) ----
__device__ int     g_cnt[NMAX];                  // per-node in-degree (excl self loop)
__device__ int     g_colS[(size_t)NMAX * SLOT];  // slotted adjacency (src indices)
__device__ float   g_dinv[NMAX];                 // (deg incl self loop)^-1/2
__device__ __half2 g_t2[(NMAX + 1) * 32];        // gather operand; row NMAX = zeros (pad)
__device__ __half2 g_h2[NMAX * 32];              // activations fp16

// ---------------- graph build ----------------

__global__ void k_fill(const int* __restrict__ ei, int e) {
    int i = blockIdx.x * blockDim.x + threadIdx.x;
    if (i >= e) return;
    int src = ei[i];
    int dst = ei[e + i];
    int pos = atomicAdd(&g_cnt[dst], 1);
    if (pos < SLOT) g_colS[(size_t)dst * SLOT + pos] = src;
}

// ---------------- prescale t2 by dinv[row]; computes + stores dinv inline ----------------
// grid-stride, 4 uint4 per thread; one wave on chip.

__global__ void __launch_bounds__(256) k_scale(__half2* __restrict__ t2, int n) {
    int stride = blockDim.x * gridDim.x;
    int tot = n * 8;
    for (int i = blockIdx.x * blockDim.x + threadIdx.x; i < tot; i += stride) {
        int row = i >> 3;
        float d = rsqrtf((float)(g_cnt[row] + 1));
        if ((i & 7) == 0) g_dinv[row] = d;
        __half2 d2 = __half2half2(__float2half_rn(d));
        uint4* p = (uint4*)t2 + i;
        uint4 v = *p;
        __half2* hp = (__half2*)&v;
        hp[0] = __hmul2(hp[0], d2);
        hp[1] = __hmul2(hp[1], d2);
        hp[2] = __hmul2(hp[2], d2);
        hp[3] = __hmul2(hp[3], d2);
        *p = v;
    }
}

// ---------------- dense GEMM via HMMA: Y[rbase+...][F] = X @ W ----------------
// 256 threads / 8 warps, 128 rows/block; warp tile 16 x F; mma.m16n8k16 f16->f32.
// SCALE: multiply output row r by dinv[r]. rbase: first row of this launch.

template <int F, bool HALF_IN, bool HALF_OUT, bool SCALE>
__global__ void __launch_bounds__(256) k_gemm_mma(
    const float* __restrict__ Xf, const __half2* __restrict__ Xh,
    const float* __restrict__ W, const float* __restrict__ bias,
    const float* __restrict__ dinv,
    float* __restrict__ Yf, __half2* __restrict__ Yh, int rbase, int n)
{
    __shared__ __half Xs[128 * 72];   // 18 KB
    __shared__ __half Ws[F * 72];
    int t  = threadIdx.x;
    int r0 = rbase + blockIdx.x * 128;

    for (int i = t; i < 128 * 32; i += 256) {
        int r = i >> 5, c2 = i & 31;
        __half2 hv;
        if (r0 + r < n) {
            if (HALF_IN) {
                hv = Xh[(size_t)(r0 + r) * 32 + c2];
            } else {
                float2 v = *(const float2*)&Xf[(size_t)(r0 + r) * 64 + c2 * 2];
                hv = __floats2half2_rn(v.x, v.y);
            }
        } else {
            hv = __floats2half2_rn(0.f, 0.f);
        }
        *(__half2*)&Xs[r * 72 + c2 * 2] = hv;
    }
    for (int i = t; i < F * 32; i += 256) {
        int c = i % F, k2 = i / F;
        __half2 hv = __floats2half2_rn(W[(2 * k2) * F + c], W[(2 * k2 + 1) * F + c]);
        *(__half2*)&Ws[c * 72 + k2 * 2] = hv;
    }
    __syncthreads();

    int lane = t & 31, w = t >> 5;
    int rw = w * 16;
    int g  = lane >> 2;
    int qc = (lane & 3) * 2;
    constexpr int NT = F / 8;

    float acc[NT][4];
#pragma unroll
    for (int j = 0; j < NT; j++)
#pragma unroll
        for (int q = 0; q < 4; q++) acc[j][q] = 0.f;

#pragma unroll
    for (int kt = 0; kt < 4; kt++) {
        int kb = kt * 16;
        unsigned a0 = *(const unsigned*)&Xs[(rw + g) * 72 + kb + qc];
        unsigned a1 = *(const unsigned*)&Xs[(rw + g + 8) * 72 + kb + qc];
        unsigned a2 = *(const unsigned*)&Xs[(rw + g) * 72 + kb + qc + 8];
        unsigned a3 = *(const unsigned*)&Xs[(rw + g + 8) * 72 + kb + qc + 8];
#pragma unroll
        for (int j = 0; j < NT; j++) {
            unsigned b0 = *(const unsigned*)&Ws[(j * 8 + g) * 72 + kb + qc];
            unsigned b1 = *(const unsigned*)&Ws[(j * 8 + g) * 72 + kb + qc + 8];
            asm volatile(
                "mma.sync.aligned.m16n8k16.row.col.f32.f16.f16.f32 "
                "{%0,%1,%2,%3}, {%4,%5,%6,%7}, {%8,%9}, {%0,%1,%2,%3};"
                : "+f"(acc[j][0]), "+f"(acc[j][1]), "+f"(acc[j][2]), "+f"(acc[j][3])
                : "r"(a0), "r"(a1), "r"(a2), "r"(a3), "r"(b0), "r"(b1));
        }
    }

    int R0 = r0 + rw + g;
    int R1 = R0 + 8;
    if (HALF_OUT) {
        float s0 = 1.f, s1 = 1.f;
        if (SCALE) {
            if (R0 < n) s0 = dinv[R0];
            if (R1 < n) s1 = dinv[R1];
        }
#pragma unroll
        for (int j = 0; j < NT; j++) {
            int col2 = (j * 8 + qc) >> 1;
            if (R0 < n) Yh[(size_t)R0 * 32 + col2] =
                __floats2half2_rn(acc[j][0] * s0, acc[j][1] * s0);
            if (R1 < n) Yh[(size_t)R1 * 32 + col2] =
                __floats2half2_rn(acc[j][2] * s1, acc[j][3] * s1);
        }
    } else {
#pragma unroll
        for (int j = 0; j < NT; j++) {
            int col = j * 8 + qc;
            float bx = bias[col], by = bias[col + 1];
            if (R0 < n) *(float2*)&Yf[(size_t)R0 * F + col] =
                make_float2(acc[j][0] + bx, acc[j][1] + by);
            if (R1 < n) *(float2*)&Yf[(size_t)R1 * F + col] =
                make_float2(acc[j][2] + bx, acc[j][3] + by);
        }
    }
}

// ---------------- aggregation (unweighted; t prescaled by dinv[src]) ----------------
// One warp per dst row in [rbase, rbase+nrows). 4 edges per iteration.
// Self-loop folded into the chunk (pad lane at position c maps to row itself);
// deeper pad lanes index the zero row. fp16 group partials, fp32 reduction.

__global__ void __launch_bounds__(256) k_agg(const __half2* __restrict__ t2,
                                             __half2* __restrict__ hout,
                                             const float* __restrict__ bias,
                                             int rbase, int nrows) {
    int gid  = (blockIdx.x * blockDim.x + threadIdx.x) >> 5;
    int lane = threadIdx.x & 31;
    if (gid >= nrows) return;
    int row = rbase + gid;
    int group = lane >> 3;
    int fl    = lane & 7;
    int c = g_cnt[row];
    if (c > SLOT) c = SLOT;
    int ce = c + 1;   // incl self loop
    float d = g_dinv[row];
    const uint4* t4 = (const uint4*)t2;
    const int* colrow = &g_colS[(size_t)row * SLOT];

    __half2 hacc[4];
#pragma unroll
    for (int j = 0; j < 4; j++) hacc[j] = __floats2half2_rn(0.f, 0.f);

    for (int b = 0; b < ce; b += 32) {
        int m = min(32, ce - b);
        int bl = b + lane;
        int idx = NMAX;                               // zero-row pad
        if (lane < m) idx = (bl < c) ? colrow[bl] : row;   // position c = self
        for (int u = 0; u < m; u += 4) {
            int src = __shfl_sync(0xffffffffu, idx, u + group);
            uint4 v = t4[(size_t)src * 8 + fl];
            const __half2* hp = (const __half2*)&v;
            hacc[0] = __hadd2(hacc[0], hp[0]);
            hacc[1] = __hadd2(hacc[1], hp[1]);
            hacc[2] = __hadd2(hacc[2], hp[2]);
            hacc[3] = __hadd2(hacc[3], hp[3]);
        }
    }

    float acc[8];
#pragma unroll
    for (int j = 0; j < 4; j++) {
        float2 p = __half22float2(hacc[j]);
        acc[2 * j]     = p.x;
        acc[2 * j + 1] = p.y;
    }
#pragma unroll
    for (int j = 0; j < 8; j++)
        acc[j] += __shfl_down_sync(0xffffffffu, acc[j], 16);
#pragma unroll
    for (int j = 0; j < 8; j++)
        acc[j] += __shfl_down_sync(0xffffffffu, acc[j], 8);

    if (lane < 8) {
        int f0 = lane * 8;
        float o[8];
#pragma unroll
        for (int j = 0; j < 8; j++)
            o[j] = fmaxf(fmaf(d, acc[j], bias[f0 + j]), 0.f);
        __half2 p0 = __floats2half2_rn(o[0], o[1]);
        __half2 p1 = __floats2half2_rn(o[2], o[3]);
        __half2 p2 = __floats2half2_rn(o[4], o[5]);
        __half2 p3 = __floats2half2_rn(o[6], o[7]);
        uint4 st = make_uint4(*(unsigned*)&p0, *(unsigned*)&p1,
                              *(unsigned*)&p2, *(unsigned*)&p3);
        *(uint4*)&hout[(size_t)row * 32 + lane * 4] = st;
    }
}

// ---------------- launch ----------------

extern "C" void kernel_launch(void* const* d_in, const int* in_sizes, int n_in,
                              void* d_out, int out_size) {
    const float* x  = (const float*)d_in[0];
    const int*   ei = (const int*)d_in[1];
    const float* W1 = (const float*)d_in[2];
    const float* b1 = (const float*)d_in[3];
    const float* W2 = (const float*)d_in[4];
    const float* b2 = (const float*)d_in[5];
    const float* Wl = (const float*)d_in[6];
    const float* bl = (const float*)d_in[7];
    float* out = (float*)d_out;

    int n = in_sizes[0] / 64;   // 100000
    int e = in_sizes[1] / 2;    // 1000000

    __half2* t2_ptr = nullptr;
    __half2* h2_ptr = nullptr;
    int*     cnt_ptr = nullptr;
    float*   dinv_ptr = nullptr;
    cudaGetSymbolAddress((void**)&t2_ptr, g_t2);
    cudaGetSymbolAddress((void**)&h2_ptr, g_h2);
    cudaGetSymbolAddress((void**)&cnt_ptr, g_cnt);
    cudaGetSymbolAddress((void**)&dinv_ptr, g_dinv);

    static cudaStream_t sB = nullptr;
    static cudaEvent_t ev_fork = nullptr, ev_join = nullptr, ev_scale = nullptr;
    static cudaEvent_t ev_g2a = nullptr, ev_g2b = nullptr, ev_endB = nullptr;
    if (sB == nullptr) {
        cudaStreamCreateWithFlags(&sB, cudaStreamNonBlocking);
        cudaEventCreateWithFlags(&ev_fork, cudaEventDisableTiming);
        cudaEventCreateWithFlags(&ev_join, cudaEventDisableTiming);
        cudaEventCreateWithFlags(&ev_scale, cudaEventDisableTiming);
        cudaEventCreateWithFlags(&ev_g2a, cudaEventDisableTiming);
        cudaEventCreateWithFlags(&ev_g2b, cudaEventDisableTiming);
        cudaEventCreateWithFlags(&ev_endB, cudaEventDisableTiming);
    }

    // row halves (gemm-block aligned)
    int nh  = ((n / 2 + 127) / 128) * 128;   // 50048
    int nr1 = n - nh;                        // second-half rows
    int gb0 = nh / 128;                      // 391
    int gb1 = (nr1 + 127) / 128;             // 391
    int ab0 = (nh + 7) / 8;
    int ab1 = (nr1 + 7) / 8;

    // fork: GEMM1 (t = x @ W1 -> fp16, unscaled) on stream B
    cudaEventRecord(ev_fork, 0);
    cudaStreamWaitEvent(sB, ev_fork, 0);
    k_gemm_mma<64, false, true, false><<<gb0 + gb1, 256, 0, sB>>>(
        x, nullptr, W1, nullptr, nullptr, nullptr, t2_ptr, 0, n);
    cudaEventRecord(ev_join, sB);

    // graph build on main stream (overlaps GEMM1); zero the pad row of t2
    cudaMemsetAsync(cnt_ptr, 0, (size_t)n * sizeof(int));
    cudaMemsetAsync(t2_ptr + (size_t)NMAX * 32, 0, 32 * sizeof(__half2));
    k_fill<<<(e + 255) / 256, 256>>>(ei, e);

    // join; prescale t1 by dinv (computes dinv inline)
    cudaStreamWaitEvent(0, ev_join, 0);
    k_scale<<<782, 256>>>(t2_ptr, n);
    cudaEventRecord(ev_scale, 0);
    cudaStreamWaitEvent(sB, ev_scale, 0);

    // pipelined tail: stream 0 owns rows [0, nh), stream B owns rows [nh, n)
    // layer-1 aggregation halves
    k_agg<<<ab0, 256>>>(t2_ptr, h2_ptr, b1, 0, nh);
    k_agg<<<ab1, 256, 0, sB>>>(t2_ptr, h2_ptr, b1, nh, nr1);
    // layer-2 GEMM halves (each needs only its own h2 rows; prescales by dinv)
    k_gemm_mma<64, true, true, true><<<gb0, 256>>>(
        nullptr, h2_ptr, W2, nullptr, dinv_ptr, nullptr, t2_ptr, 0, n);
    cudaEventRecord(ev_g2a, 0);
    k_gemm_mma<64, true, true, true><<<gb1, 256, 0, sB>>>(
        nullptr, h2_ptr, W2, nullptr, dinv_ptr, nullptr, t2_ptr, nh, n);
    cudaEventRecord(ev_g2b, sB);
    // layer-2 aggregation needs ALL of t2 -> cross-wait
    cudaStreamWaitEvent(0, ev_g2b, 0);
    cudaStreamWaitEvent(sB, ev_g2a, 0);
    k_agg<<<ab0, 256>>>(t2_ptr, h2_ptr, b2, 0, nh);
    k_agg<<<ab1, 256, 0, sB>>>(t2_ptr, h2_ptr, b2, nh, nr1);
    // classifier halves (row-local)
    k_gemm_mma<32, true, false, false><<<gb0, 256>>>(
        nullptr, h2_ptr, Wl, bl, nullptr, out, nullptr, 0, n);
    k_gemm_mma<32, true, false, false><<<gb1, 256, 0, sB>>>(
        nullptr, h2_ptr, Wl, bl, nullptr, out, nullptr, nh, n);
    cudaEventRecord(ev_endB, sB);
    cudaStreamWaitEvent(0, ev_endB, 0);
}

// round 16
// speedup vs baseline: 1.0684x; 1.0178x over previous
#include <cuda_runtime.h>
#include <cuda_fp16.h>

#define NMAX 100000
#define EMAX 1000000
#define SLOT 64

// ---- scratch (device globals; no allocation allowed) ----
__device__ int     g_cnt[NMAX];                  // per-node in-degree (excl self loop)
__device__ int     g_colS[(size_t)NMAX * SLOT];  // slotted adjacency (src indices)
__device__ float   g_dinv[NMAX];                 // (deg incl self loop)^-1/2
__device__ __half2 g_t2[(NMAX + 1) * 32];        // gather operand; row NMAX = zeros (pad)
__device__ __half2 g_h2[NMAX * 32];              // activations fp16

// ---------------- graph build ----------------

__global__ void k_fill(const int* __restrict__ ei, int e) {
    int i = blockIdx.x * blockDim.x + threadIdx.x;
    if (i >= e) return;
    int src = ei[i];
    int dst = ei[e + i];
    int pos = atomicAdd(&g_cnt[dst], 1);
    if (pos < SLOT) g_colS[(size_t)dst * SLOT + pos] = src;
}

// ---------------- prescale t2 by dinv[row]; computes + stores dinv inline ----------------

__global__ void __launch_bounds__(256) k_scale(__half2* __restrict__ t2, int n) {
    int stride = blockDim.x * gridDim.x;
    int tot = n * 8;
    for (int i = blockIdx.x * blockDim.x + threadIdx.x; i < tot; i += stride) {
        int row = i >> 3;
        float d = rsqrtf((float)(g_cnt[row] + 1));
        if ((i & 7) == 0) g_dinv[row] = d;
        __half2 d2 = __half2half2(__float2half_rn(d));
        uint4* p = (uint4*)t2 + i;
        uint4 v = *p;
        __half2* hp = (__half2*)&v;
        hp[0] = __hmul2(hp[0], d2);
        hp[1] = __hmul2(hp[1], d2);
        hp[2] = __hmul2(hp[2], d2);
        hp[3] = __hmul2(hp[3], d2);
        *p = v;
    }
}

// ---------------- dense GEMM via HMMA: Y[rbase+...][F] = X @ W ----------------

template <int F, bool HALF_IN, bool HALF_OUT, bool SCALE>
__global__ void __launch_bounds__(256) k_gemm_mma(
    const float* __restrict__ Xf, const __half2* __restrict__ Xh,
    const float* __restrict__ W, const float* __restrict__ bias,
    const float* __restrict__ dinv,
    float* __restrict__ Yf, __half2* __restrict__ Yh, int rbase, int n)
{
    __shared__ __half Xs[128 * 72];   // 18 KB
    __shared__ __half Ws[F * 72];
    int t  = threadIdx.x;
    int r0 = rbase + blockIdx.x * 128;

    for (int i = t; i < 128 * 32; i += 256) {
        int r = i >> 5, c2 = i & 31;
        __half2 hv;
        if (r0 + r < n) {
            if (HALF_IN) {
                hv = Xh[(size_t)(r0 + r) * 32 + c2];
            } else {
                float2 v = *(const float2*)&Xf[(size_t)(r0 + r) * 64 + c2 * 2];
                hv = __floats2half2_rn(v.x, v.y);
            }
        } else {
            hv = __floats2half2_rn(0.f, 0.f);
        }
        *(__half2*)&Xs[r * 72 + c2 * 2] = hv;
    }
    for (int i = t; i < F * 32; i += 256) {
        int c = i % F, k2 = i / F;
        __half2 hv = __floats2half2_rn(W[(2 * k2) * F + c], W[(2 * k2 + 1) * F + c]);
        *(__half2*)&Ws[c * 72 + k2 * 2] = hv;
    }
    __syncthreads();

    int lane = t & 31, w = t >> 5;
    int rw = w * 16;
    int g  = lane >> 2;
    int qc = (lane & 3) * 2;
    constexpr int NT = F / 8;

    float acc[NT][4];
#pragma unroll
    for (int j = 0; j < NT; j++)
#pragma unroll
        for (int q = 0; q < 4; q++) acc[j][q] = 0.f;

#pragma unroll
    for (int kt = 0; kt < 4; kt++) {
        int kb = kt * 16;
        unsigned a0 = *(const unsigned*)&Xs[(rw + g) * 72 + kb + qc];
        unsigned a1 = *(const unsigned*)&Xs[(rw + g + 8) * 72 + kb + qc];
        unsigned a2 = *(const unsigned*)&Xs[(rw + g) * 72 + kb + qc + 8];
        unsigned a3 = *(const unsigned*)&Xs[(rw + g + 8) * 72 + kb + qc + 8];
#pragma unroll
        for (int j = 0; j < NT; j++) {
            unsigned b0 = *(const unsigned*)&Ws[(j * 8 + g) * 72 + kb + qc];
            unsigned b1 = *(const unsigned*)&Ws[(j * 8 + g) * 72 + kb + qc + 8];
            asm volatile(
                "mma.sync.aligned.m16n8k16.row.col.f32.f16.f16.f32 "
                "{%0,%1,%2,%3}, {%4,%5,%6,%7}, {%8,%9}, {%0,%1,%2,%3};"
                : "+f"(acc[j][0]), "+f"(acc[j][1]), "+f"(acc[j][2]), "+f"(acc[j][3])
                : "r"(a0), "r"(a1), "r"(a2), "r"(a3), "r"(b0), "r"(b1));
        }
    }

    int R0 = r0 + rw + g;
    int R1 = R0 + 8;
    if (HALF_OUT) {
        float s0 = 1.f, s1 = 1.f;
        if (SCALE) {
            if (R0 < n) s0 = dinv[R0];
            if (R1 < n) s1 = dinv[R1];
        }
#pragma unroll
        for (int j = 0; j < NT; j++) {
            int col2 = (j * 8 + qc) >> 1;
            if (R0 < n) Yh[(size_t)R0 * 32 + col2] =
                __floats2half2_rn(acc[j][0] * s0, acc[j][1] * s0);
            if (R1 < n) Yh[(size_t)R1 * 32 + col2] =
                __floats2half2_rn(acc[j][2] * s1, acc[j][3] * s1);
        }
    } else {
#pragma unroll
        for (int j = 0; j < NT; j++) {
            int col = j * 8 + qc;
            float bx = bias[col], by = bias[col + 1];
            if (R0 < n) *(float2*)&Yf[(size_t)R0 * F + col] =
                make_float2(acc[j][0] + bx, acc[j][1] + by);
            if (R1 < n) *(float2*)&Yf[(size_t)R1 * F + col] =
                make_float2(acc[j][2] + bx, acc[j][3] + by);
        }
    }
}

// ---------------- aggregation (unweighted; t prescaled by dinv[src]) ----------------
// One warp per dst row. 8 edges per iteration: 2 shfl'd pre-multiplied indices,
// 2 independent LDG.128 gathers in flight per group (group = lane>>3, 8 lanes x
// uint4 per row). Self-loop folded at chunk position c; pad lanes -> zero row.
// fp16 group partials, fp32 cross-group reduction. h = relu(d*sum + b), fp16.

__global__ void __launch_bounds__(256) k_agg(const __half2* __restrict__ t2,
                                             __half2* __restrict__ hout,
                                             const float* __restrict__ bias,
                                             int rbase, int nrows) {
    int gid  = (blockIdx.x * blockDim.x + threadIdx.x) >> 5;
    int lane = threadIdx.x & 31;
    if (gid >= nrows) return;
    int row = rbase + gid;
    int group = lane >> 3;
    int fl    = lane & 7;
    int c = g_cnt[row];
    if (c > SLOT) c = SLOT;
    int ce = c + 1;   // incl self loop
    float d = g_dinv[row];
    const uint4* t4f = (const uint4*)t2 + fl;   // per-lane base (feature octet)
    const int* colrow = &g_colS[(size_t)row * SLOT];

    __half2 hacc[4];
#pragma unroll
    for (int j = 0; j < 4; j++) hacc[j] = __floats2half2_rn(0.f, 0.f);

    for (int b = 0; b < ce; b += 32) {
        int m = min(32, ce - b);
        int bl = b + lane;
        int idx8 = NMAX * 8;                                   // zero-row pad
        if (lane < m) idx8 = ((bl < c) ? colrow[bl] : row) * 8;  // position c = self
        for (int u = 0; u < m; u += 8) {
            int s0 = __shfl_sync(0xffffffffu, idx8, u + group);
            int s1 = __shfl_sync(0xffffffffu, idx8, u + 4 + group);
            uint4 v0 = t4f[s0];          // two gathers in flight
            uint4 v1 = t4f[s1];
            const __half2* h0 = (const __half2*)&v0;
            const __half2* h1 = (const __half2*)&v1;
            hacc[0] = __hadd2(hacc[0], h0[0]);
            hacc[1] = __hadd2(hacc[1], h0[1]);
            hacc[2] = __hadd2(hacc[2], h0[2]);
            hacc[3] = __hadd2(hacc[3], h0[3]);
            hacc[0] = __hadd2(hacc[0], h1[0]);
            hacc[1] = __hadd2(hacc[1], h1[1]);
            hacc[2] = __hadd2(hacc[2], h1[2]);
            hacc[3] = __hadd2(hacc[3], h1[3]);
        }
    }

    float acc[8];
#pragma unroll
    for (int j = 0; j < 4; j++) {
        float2 p = __half22float2(hacc[j]);
        acc[2 * j]     = p.x;
        acc[2 * j + 1] = p.y;
    }
#pragma unroll
    for (int j = 0; j < 8; j++)
        acc[j] += __shfl_down_sync(0xffffffffu, acc[j], 16);
#pragma unroll
    for (int j = 0; j < 8; j++)
        acc[j] += __shfl_down_sync(0xffffffffu, acc[j], 8);

    if (lane < 8) {
        int f0 = lane * 8;
        float o[8];
#pragma unroll
        for (int j = 0; j < 8; j++)
            o[j] = fmaxf(fmaf(d, acc[j], bias[f0 + j]), 0.f);
        __half2 p0 = __floats2half2_rn(o[0], o[1]);
        __half2 p1 = __floats2half2_rn(o[2], o[3]);
        __half2 p2 = __floats2half2_rn(o[4], o[5]);
        __half2 p3 = __floats2half2_rn(o[6], o[7]);
        uint4 st = make_uint4(*(unsigned*)&p0, *(unsigned*)&p1,
                              *(unsigned*)&p2, *(unsigned*)&p3);
        *(uint4*)&hout[(size_t)row * 32 + lane * 4] = st;
    }
}

// ---------------- launch ----------------

extern "C" void kernel_launch(void* const* d_in, const int* in_sizes, int n_in,
                              void* d_out, int out_size) {
    const float* x  = (const float*)d_in[0];
    const int*   ei = (const int*)d_in[1];
    const float* W1 = (const float*)d_in[2];
    const float* b1 = (const float*)d_in[3];
    const float* W2 = (const float*)d_in[4];
    const float* b2 = (const float*)d_in[5];
    const float* Wl = (const float*)d_in[6];
    const float* bl = (const float*)d_in[7];
    float* out = (float*)d_out;

    int n = in_sizes[0] / 64;   // 100000
    int e = in_sizes[1] / 2;    // 1000000

    __half2* t2_ptr = nullptr;
    __half2* h2_ptr = nullptr;
    int*     cnt_ptr = nullptr;
    float*   dinv_ptr = nullptr;
    cudaGetSymbolAddress((void**)&t2_ptr, g_t2);
    cudaGetSymbolAddress((void**)&h2_ptr, g_h2);
    cudaGetSymbolAddress((void**)&cnt_ptr, g_cnt);
    cudaGetSymbolAddress((void**)&dinv_ptr, g_dinv);

    static cudaStream_t sB = nullptr;
    static cudaEvent_t ev_fork = nullptr, ev_join = nullptr, ev_scale = nullptr;
    static cudaEvent_t ev_g2a = nullptr, ev_g2b = nullptr, ev_endB = nullptr;
    if (sB == nullptr) {
        cudaStreamCreateWithFlags(&sB, cudaStreamNonBlocking);
        cudaEventCreateWithFlags(&ev_fork, cudaEventDisableTiming);
        cudaEventCreateWithFlags(&ev_join, cudaEventDisableTiming);
        cudaEventCreateWithFlags(&ev_scale, cudaEventDisableTiming);
        cudaEventCreateWithFlags(&ev_g2a, cudaEventDisableTiming);
        cudaEventCreateWithFlags(&ev_g2b, cudaEventDisableTiming);
        cudaEventCreateWithFlags(&ev_endB, cudaEventDisableTiming);
    }

    // row halves (gemm-block aligned)
    int nh  = ((n / 2 + 127) / 128) * 128;   // 50048
    int nr1 = n - nh;
    int gb0 = nh / 128;
    int gb1 = (nr1 + 127) / 128;
    int ab0 = (nh + 7) / 8;
    int ab1 = (nr1 + 7) / 8;

    // fork: GEMM1 (t = x @ W1 -> fp16, unscaled) on stream B
    cudaEventRecord(ev_fork, 0);
    cudaStreamWaitEvent(sB, ev_fork, 0);
    k_gemm_mma<64, false, true, false><<<gb0 + gb1, 256, 0, sB>>>(
        x, nullptr, W1, nullptr, nullptr, nullptr, t2_ptr, 0, n);
    cudaEventRecord(ev_join, sB);

    // graph build on main stream (overlaps GEMM1); zero the pad row of t2
    cudaMemsetAsync(cnt_ptr, 0, (size_t)n * sizeof(int));
    cudaMemsetAsync(t2_ptr + (size_t)NMAX * 32, 0, 32 * sizeof(__half2));
    k_fill<<<(e + 255) / 256, 256>>>(ei, e);

    // join; prescale t1 by dinv (computes dinv inline)
    cudaStreamWaitEvent(0, ev_join, 0);
    k_scale<<<782, 256>>>(t2_ptr, n);
    cudaEventRecord(ev_scale, 0);
    cudaStreamWaitEvent(sB, ev_scale, 0);

    // pipelined tail: stream 0 owns rows [0, nh), stream B owns rows [nh, n)
    k_agg<<<ab0, 256>>>(t2_ptr, h2_ptr, b1, 0, nh);
    k_agg<<<ab1, 256, 0, sB>>>(t2_ptr, h2_ptr, b1, nh, nr1);
    k_gemm_mma<64, true, true, true><<<gb0, 256>>>(
        nullptr, h2_ptr, W2, nullptr, dinv_ptr, nullptr, t2_ptr, 0, n);
    cudaEventRecord(ev_g2a, 0);
    k_gemm_mma<64, true, true, true><<<gb1, 256, 0, sB>>>(
        nullptr, h2_ptr, W2, nullptr, dinv_ptr, nullptr, t2_ptr, nh, n);
    cudaEventRecord(ev_g2b, sB);
    cudaStreamWaitEvent(0, ev_g2b, 0);
    cudaStreamWaitEvent(sB, ev_g2a, 0);
    k_agg<<<ab0, 256>>>(t2_ptr, h2_ptr, b2, 0, nh);
    k_agg<<<ab1, 256, 0, sB>>>(t2_ptr, h2_ptr, b2, nh, nr1);
    k_gemm_mma<32, true, false, false><<<gb0, 256>>>(
        nullptr, h2_ptr, Wl, bl, nullptr, out, nullptr, 0, n);
    k_gemm_mma<32, true, false, false><<<gb1, 256, 0, sB>>>(
        nullptr, h2_ptr, Wl, bl, nullptr, out, nullptr, nh, n);
    cudaEventRecord(ev_endB, sB);
    cudaStreamWaitEvent(0, ev_endB, 0);
}